// round 15
// baseline (speedup 1.0000x reference)
#include <cuda_runtime.h>
#include <cuda_fp16.h>
#include <cstdint>

#define NB 4
#define NC 256
#define NK 32
#define NPOS 4096
#define QM 128
#define TK 128
#define NT (NPOS / TK)    // 32
#define THREADS 512
#define LOG2E 1.4426950408889634f

// ---------------- scratch (device globals; no allocs allowed) ---------------
__device__ __align__(128) __half g_Q[(size_t)NB * NK * NPOS];   // [b][c][n]
__device__ __align__(128) __half g_K[(size_t)NB * NK * NPOS];   // [b][c][n]
__device__ __align__(128) __half g_V[(size_t)NB * NC * NPOS];   // [b][d][n]

// ---------------- helpers ---------------------------------------------------
__device__ __forceinline__ uint32_t s2u(const void* p) {
    uint32_t a;
    asm("{ .reg .u64 t; cvta.to.shared.u64 t, %1; cvt.u32.u64 %0, t; }"
        : "=r"(a) : "l"(p));
    return a;
}
__device__ __forceinline__ void cp16(uint32_t s, const void* g) {
    asm volatile("cp.async.cg.shared.global [%0], [%1], 16;" :: "r"(s), "l"(g));
}
#define CP_COMMIT() asm volatile("cp.async.commit_group;" ::: "memory")
#define CP_WAIT(n)  asm volatile("cp.async.wait_group %0;" :: "n"(n) : "memory")

__device__ __forceinline__ float ex2f(float x) {
    float r; asm("ex2.approx.f32 %0, %1;" : "=f"(r) : "f"(x)); return r;
}
__device__ __forceinline__ void mma16(float* c, const uint32_t* a,
                                      uint32_t b0, uint32_t b1) {
    asm volatile(
        "mma.sync.aligned.m16n8k16.row.col.f32.f16.f16.f32 "
        "{%0,%1,%2,%3}, {%4,%5,%6,%7}, {%8,%9}, {%0,%1,%2,%3};"
        : "+f"(c[0]), "+f"(c[1]), "+f"(c[2]), "+f"(c[3])
        : "r"(a[0]), "r"(a[1]), "r"(a[2]), "r"(a[3]), "r"(b0), "r"(b1));
}
__device__ __forceinline__ void mma16h(uint32_t* c, const uint32_t* a,
                                       uint32_t b0, uint32_t b1) {
    asm volatile(
        "mma.sync.aligned.m16n8k16.row.col.f16.f16.f16.f16 "
        "{%0,%1}, {%2,%3,%4,%5}, {%6,%7}, {%0,%1};"
        : "+r"(c[0]), "+r"(c[1])
        : "r"(a[0]), "r"(a[1]), "r"(a[2]), "r"(a[3]), "r"(b0), "r"(b1));
}
__device__ __forceinline__ void ldsm4(uint32_t* r, uint32_t saddr) {
    asm volatile("ldmatrix.sync.aligned.m8n8.x4.shared.b16 {%0,%1,%2,%3}, [%4];"
        : "=r"(r[0]), "=r"(r[1]), "=r"(r[2]), "=r"(r[3]) : "r"(saddr));
}
__device__ __forceinline__ void ldsm4t(uint32_t* r, uint32_t saddr) {
    asm volatile("ldmatrix.sync.aligned.m8n8.x4.trans.shared.b16 {%0,%1,%2,%3}, [%4];"
        : "=r"(r[0]), "=r"(r[1]), "=r"(r[2]), "=r"(r[3]) : "r"(saddr));
}

// ---- attn smem (halfs / bytes) ----
#define QSTR 136
#define KSTR 136
#define VSH 136
#define PSH 136
#define SM_Q 0
#define QTILEB (32 * QSTR * 2)                 // 8704
#define SM_K (SM_Q + QTILEB)                   // 8704
#define KBUFB (32 * KSTR * 2)                  // 8704
#define SM_V (SM_K + 2 * KBUFB)                // 26112
#define VBUFB (NC * VSH * 2)                   // 69632
#define SM_P (SM_V + 2 * VBUFB)                // 165376
#define SM_L (SM_P + QM * PSH * 2)             // 200192
#define SMEM_BYTES (SM_L + 4 * QM * 4)         // 202240

// ---- proj smem ----
#define AST 264
#define BST 264
#define PROJ_A_B (64 * AST * 2)                // 33792
#define PROJ_BBUF (32 * BST * 2)               // 16896
#define PROJ_SMEM (PROJ_A_B + 2 * PROJ_BBUF)   // 67584

// ---------------------------------------------------------------------------
// Projection fp16 GEMM. W read fp32 and converted inline into the A tile
// (cvt_w kernel eliminated); x read fp32, converted per chunk.
// ---------------------------------------------------------------------------
__global__ __launch_bounds__(256, 2) void proj_kernel(
    const float* __restrict__ x, const float* __restrict__ w1,
    const float* __restrict__ w2, const float* __restrict__ w3)
{
    extern __shared__ __half PH[];
    const uint32_t sA = s2u(PH);
    __half* Bh = PH + PROJ_A_B / 2;

    const int n0 = blockIdx.x * 256;
    const int k0 = blockIdx.y * 64;
    const int b  = blockIdx.z;
    const int t  = threadIdx.x;
    const int wid = t >> 5, lid = t & 31;
    const int mw = wid & 3, nh = wid >> 2;
    const int gid = lid >> 2, tig = lid & 3;

    const float* xb = x + (size_t)b * NC * NPOS + n0;

    // A tile: 64 rows x 256 c, fp32 LDG -> fp16 STS (with log2e on Q rows)
    {
#pragma unroll
        for (int s = 0; s < 8; s++) {
            int i = t + s * 256;
            int r = i >> 5, o = i & 31;          // row, 8-float group
            int kg = k0 + r;
            const float* wp; float sc;
            if (kg < 32)      { wp = w1 + kg * 256;        sc = LOG2E; }
            else if (kg < 64) { wp = w2 + (kg - 32) * 256; sc = 1.f; }
            else              { wp = w3 + (kg - 64) * 256; sc = 1.f; }
            float4 a0 = *(const float4*)(wp + o * 8);
            float4 a1 = *(const float4*)(wp + o * 8 + 4);
            __half2 h[4];
            h[0] = __floats2half2_rn(a0.x * sc, a0.y * sc);
            h[1] = __floats2half2_rn(a0.z * sc, a0.w * sc);
            h[2] = __floats2half2_rn(a1.x * sc, a1.y * sc);
            h[3] = __floats2half2_rn(a1.z * sc, a1.w * sc);
            *(uint4*)(PH + r * AST + o * 8) = *(uint4*)h;
        }
    }

    // prefetch B chunk 0 into registers
    float4 xv[8];
#pragma unroll
    for (int s = 0; s < 8; s++) {
        int i = t + s * 256;
        int c = i >> 6, n4 = i & 63;
        xv[s] = *(const float4*)(xb + (size_t)c * NPOS + n4 * 4);
    }

    __syncthreads();   // A tile visible to all warps

    float o[16][4];
#pragma unroll
    for (int n = 0; n < 16; n++)
#pragma unroll
        for (int c = 0; c < 4; c++) o[n][c] = 0.f;

    for (int ci = 0; ci < 8; ci++) {
        const int buf = ci & 1;
        __half* Bb = Bh + buf * (32 * BST);
#pragma unroll
        for (int s = 0; s < 8; s++) {
            int i = t + s * 256;
            int c = i >> 6, n4 = i & 63;
            __half2 h0 = __floats2half2_rn(xv[s].x, xv[s].y);
            __half2 h1 = __floats2half2_rn(xv[s].z, xv[s].w);
            *(__half2*)(Bb + c * BST + n4 * 4)     = h0;
            *(__half2*)(Bb + c * BST + n4 * 4 + 2) = h1;
        }
        __syncthreads();
        if (ci < 7) {
            const float* xc = xb + (size_t)(ci + 1) * 32 * NPOS;
#pragma unroll
            for (int s = 0; s < 8; s++) {
                int i = t + s * 256;
                int c = i >> 6, n4 = i & 63;
                xv[s] = *(const float4*)(xc + (size_t)c * NPOS + n4 * 4);
            }
        }
        const uint32_t bB = s2u(Bb);
#pragma unroll
        for (int kk2 = 0; kk2 < 2; kk2++) {
            uint32_t af[4];
            ldsm4(af, sA + ((mw * 16 + (lid & 15)) * AST +
                            ci * 32 + kk2 * 16 + ((lid >> 4) << 3)) * 2);
#pragma unroll
            for (int nb = 0; nb < 8; nb++) {
                uint32_t bf[4];
                ldsm4t(bf, bB + ((kk2 * 16 + (lid & 15)) * BST +
                                 nh * 128 + nb * 16 + ((lid >> 4) << 3)) * 2);
                mma16(o[2 * nb],     af, bf[0], bf[1]);
                mma16(o[2 * nb + 1], af, bf[2], bf[3]);
            }
        }
    }

#pragma unroll
    for (int hh = 0; hh < 2; hh++) {
        int k = k0 + mw * 16 + gid + hh * 8;
        __half* dst = (k < 32) ? g_Q + ((size_t)b * NK + k) * NPOS
                    : (k < 64) ? g_K + ((size_t)b * NK + (k - 32)) * NPOS
                               : g_V + ((size_t)b * NC + (k - 64)) * NPOS;
#pragma unroll
        for (int nb = 0; nb < 16; nb++) {
            int n = n0 + nh * 128 + nb * 8 + 2 * tig;
            *(__half2*)(dst + n) = __floats2half2_rn(o[nb][2 * hh], o[nb][2 * hh + 1]);
        }
    }
}

// ---------------------------------------------------------------------------
// fp16 flash attention with FUSED row-max pre-sweep (fp16-accum QK over all
// key tiles using the K double buffer; Q fragments loaded once, reused).
// mg = wid>>2 (32 q rows), dcW = wid&3 (32-key / 64-d slice).
// ---------------------------------------------------------------------------
__global__ __launch_bounds__(THREADS) void attn_kernel(
    const float* __restrict__ x, float* __restrict__ out)
{
    extern __shared__ __align__(16) char sm[];
    const uint32_t sb = s2u(sm);
    __half* Ps = (__half*)(sm + SM_P);
    float* SL  = (float*)(sm + SM_L);

    const int t   = threadIdx.x;
    const int wid = t >> 5, lid = t & 31;
    const int gid = lid >> 2, tig = lid & 3;
    const int mg  = wid >> 2, dcW = wid & 3;
    const int rb  = mg * 32;
    const int kbase  = dcW * 32;
    const int dstart = dcW * 64;
    const int b  = blockIdx.y;
    const int q0 = blockIdx.x * QM;

    const int qc = ((lid >> 4) << 3) | (lid & 7);
    const int qq = ((lid >> 3) & 1) << 3;
    const int kc = lid & 15;
    const int kn = (lid >> 4) << 3;
    const int arow  = lid & 15;
    const int acolh = (lid >> 4) << 3;
    const int brow  = ((lid >> 4) << 3) | (lid & 7);
    const int bcolh = ((lid >> 3) & 1) << 3;

    const __half* Qg = g_Q + (size_t)b * NK * NPOS + q0;
    const __half* Kg = g_K + (size_t)b * NK * NPOS;
    const __half* Vg = g_V + (size_t)b * NC * NPOS;

    // ================= pre-sweep: row max of s (log2 units) =================
    {
        int c = t >> 4, o = t & 15;
        cp16(sb + SM_Q + (c * QSTR + o * 8) * 2, Qg + (size_t)c * NPOS + o * 8);
        cp16(sb + SM_K + (c * KSTR + o * 8) * 2, Kg + (size_t)c * NPOS + o * 8);
        CP_COMMIT();
    }

    uint32_t qf[2][2][4];
    const __half2 NEGINF = __floats2half2_rn(-65504.f, -65504.f);
    __half2 mxh[2][2];
#pragma unroll
    for (int a = 0; a < 2; a++)
#pragma unroll
        for (int h = 0; h < 2; h++) mxh[a][h] = NEGINF;

    for (int j = 0; j < NT; j++) {
        const int cur = j & 1;
        CP_WAIT(0);
        __syncthreads();
        if (j == 0) {
#pragma unroll
            for (int rbk = 0; rbk < 2; rbk++)
#pragma unroll
                for (int kk = 0; kk < 2; kk++)
                    ldsm4t(qf[rbk][kk],
                           sb + SM_Q + ((kk * 16 + qc) * QSTR + rb + rbk * 16 + qq) * 2);
        }
        if (j + 1 < NT) {
            const size_t koff = (size_t)(j + 1) * TK;
            int c = t >> 4, o2 = t & 15;
            cp16(sb + SM_K + ((1 - cur) * 32 * KSTR + c * KSTR + o2 * 8) * 2,
                 Kg + (size_t)c * NPOS + koff + o2 * 8);
            CP_COMMIT();
        }
        const uint32_t kbB = sb + SM_K + cur * KBUFB;
#pragma unroll
        for (int nbp = 0; nbp < 2; nbp++) {
            uint32_t kf[2][4];
#pragma unroll
            for (int kk = 0; kk < 2; kk++)
                ldsm4t(kf[kk],
                       kbB + ((kk * 16 + kc) * KSTR + kbase + nbp * 16 + kn) * 2);
#pragma unroll
            for (int rbk = 0; rbk < 2; rbk++) {
                uint32_t c0[2] = {0u, 0u}, c1[2] = {0u, 0u};
#pragma unroll
                for (int kk = 0; kk < 2; kk++) {
                    mma16h(c0, qf[rbk][kk], kf[kk][0], kf[kk][1]);
                    mma16h(c1, qf[rbk][kk], kf[kk][2], kf[kk][3]);
                }
                __half2 h0 = __hmax2(*(__half2*)&c0[0], *(__half2*)&c1[0]);
                __half2 h1 = __hmax2(*(__half2*)&c0[1], *(__half2*)&c1[1]);
                mxh[rbk][0] = __hmax2(mxh[rbk][0], h0);
                mxh[rbk][1] = __hmax2(mxh[rbk][1], h1);
            }
        }
    }

    // reduce per-dcW maxes into SL, combine across dcW
    {
        float a0[2], a1[2];
#pragma unroll
        for (int rbk = 0; rbk < 2; rbk++) {
            a0[rbk] = fmaxf(__low2float(mxh[rbk][0]), __high2float(mxh[rbk][0]));
            a1[rbk] = fmaxf(__low2float(mxh[rbk][1]), __high2float(mxh[rbk][1]));
            a0[rbk] = fmaxf(a0[rbk], __shfl_xor_sync(0xffffffffu, a0[rbk], 1));
            a0[rbk] = fmaxf(a0[rbk], __shfl_xor_sync(0xffffffffu, a0[rbk], 2));
            a1[rbk] = fmaxf(a1[rbk], __shfl_xor_sync(0xffffffffu, a1[rbk], 1));
            a1[rbk] = fmaxf(a1[rbk], __shfl_xor_sync(0xffffffffu, a1[rbk], 2));
        }
        if (tig == 0) {
            SL[dcW * QM + rb + gid]      = a0[0];
            SL[dcW * QM + rb + 8 + gid]  = a1[0];
            SL[dcW * QM + rb + 16 + gid] = a0[1];
            SL[dcW * QM + rb + 24 + gid] = a1[1];
        }
    }
    __syncthreads();

    float m0[2], m1[2];
#pragma unroll
    for (int rbk = 0; rbk < 2; rbk++) {
        int r0 = rb + rbk * 16 + gid;
        m0[rbk] = fmaxf(fmaxf(SL[r0], SL[QM + r0]),
                        fmaxf(SL[2 * QM + r0], SL[3 * QM + r0]));
        int r1 = r0 + 8;
        m1[rbk] = fmaxf(fmaxf(SL[r1], SL[QM + r1]),
                        fmaxf(SL[2 * QM + r1], SL[3 * QM + r1]));
    }

    // re-prime pipeline: K0 + V0 into buffer 0
    {
        int c = t >> 4, o = t & 15;
        cp16(sb + SM_K + (c * KSTR + o * 8) * 2, Kg + (size_t)c * NPOS + o * 8);
#pragma unroll
        for (int s = 0; s < 8; s++) {
            int i = t + s * THREADS;
            int d = i >> 4, k4 = i & 15;
            cp16(sb + SM_V + (d * VSH + k4 * 8) * 2, Vg + (size_t)d * NPOS + k4 * 8);
        }
        CP_COMMIT();
    }

    // ================= main loop =================
    float o[2][8][4];
#pragma unroll
    for (int r = 0; r < 2; r++)
#pragma unroll
        for (int n = 0; n < 8; n++)
#pragma unroll
            for (int c = 0; c < 4; c++) o[r][n][c] = 0.f;

    float lacc[2][2] = {{0.f, 0.f}, {0.f, 0.f}};

    for (int j = 0; j < NT; j++) {
        const int cur = j & 1;
        CP_WAIT(0);
        __syncthreads();

        if (j + 1 < NT) {
            const size_t koff = (size_t)(j + 1) * TK;
            int c = t >> 4, o2 = t & 15;
            cp16(sb + SM_K + ((1 - cur) * 32 * KSTR + c * KSTR + o2 * 8) * 2,
                 Kg + (size_t)c * NPOS + koff + o2 * 8);
#pragma unroll
            for (int s = 0; s < 8; s++) {
                int i = t + s * THREADS;
                int d = i >> 4, k4 = i & 15;
                cp16(sb + SM_V + (1 - cur) * VBUFB + (d * VSH + k4 * 8) * 2,
                     Vg + (size_t)d * NPOS + koff + k4 * 8);
            }
            CP_COMMIT();
        }

        // ---- phase A: S = Q K^T, e = 2^(s-m), P -> smem ----
        {
            const uint32_t kbB = sb + SM_K + cur * KBUFB;
#pragma unroll
            for (int nbp = 0; nbp < 2; nbp++) {
                uint32_t kf[2][4];
#pragma unroll
                for (int kk = 0; kk < 2; kk++)
                    ldsm4t(kf[kk],
                           kbB + ((kk * 16 + kc) * KSTR + kbase + nbp * 16 + kn) * 2);
#pragma unroll
                for (int rbk = 0; rbk < 2; rbk++) {
                    float s4[2][4] = {{0.f,0.f,0.f,0.f},{0.f,0.f,0.f,0.f}};
#pragma unroll
                    for (int kk = 0; kk < 2; kk++) {
                        mma16(s4[0], qf[rbk][kk], kf[kk][0], kf[kk][1]);
                        mma16(s4[1], qf[rbk][kk], kf[kk][2], kf[kk][3]);
                    }
                    const int q = rb + rbk * 16 + gid;
#pragma unroll
                    for (int nb2 = 0; nb2 < 2; nb2++) {
                        float e0 = ex2f(s4[nb2][0] - m0[rbk]);
                        float e1 = ex2f(s4[nb2][1] - m0[rbk]);
                        float e2 = ex2f(s4[nb2][2] - m1[rbk]);
                        float e3 = ex2f(s4[nb2][3] - m1[rbk]);
                        lacc[rbk][0] += e0 + e1;
                        lacc[rbk][1] += e2 + e3;
                        const int col = kbase + nbp * 16 + nb2 * 8 + 2 * tig;
                        *(__half2*)&Ps[q * PSH + col]       = __floats2half2_rn(e0, e1);
                        *(__half2*)&Ps[(q + 8) * PSH + col] = __floats2half2_rn(e2, e3);
                    }
                }
            }
        }
        asm volatile("bar.sync %0, 128;" :: "r"(mg + 1) : "memory");

        // ---- phase B: O += P @ V ----
        {
            const uint32_t vbB = sb + SM_V + cur * VBUFB;
#pragma unroll
            for (int kk = 0; kk < 8; kk++) {
                uint32_t pf[2][4];
#pragma unroll
                for (int rbk = 0; rbk < 2; rbk++)
                    ldsm4(pf[rbk],
                          sb + SM_P + ((rb + rbk * 16 + arow) * PSH + kk * 16 + acolh) * 2);
#pragma unroll
                for (int dp = 0; dp < 4; dp++) {
                    uint32_t vf[4];
                    ldsm4(vf, vbB + ((dstart + dp * 16 + brow) * VSH + kk * 16 + bcolh) * 2);
                    mma16(o[0][2 * dp],     pf[0], vf[0], vf[1]);
                    mma16(o[0][2 * dp + 1], pf[0], vf[2], vf[3]);
                    mma16(o[1][2 * dp],     pf[1], vf[0], vf[1]);
                    mma16(o[1][2 * dp + 1], pf[1], vf[2], vf[3]);
                }
            }
        }
    }

    // ---- denominators ----
#pragma unroll
    for (int rbk = 0; rbk < 2; rbk++)
#pragma unroll
        for (int h = 0; h < 2; h++) {
            float v = lacc[rbk][h];
            v += __shfl_xor_sync(0xffffffffu, v, 1);
            v += __shfl_xor_sync(0xffffffffu, v, 2);
            lacc[rbk][h] = v;
        }
    __syncthreads();   // SL still holds maxes; ensure all reads done before overwrite
    if (tig == 0) {
        SL[dcW * QM + rb + gid]      = lacc[0][0];
        SL[dcW * QM + rb + 8 + gid]  = lacc[0][1];
        SL[dcW * QM + rb + 16 + gid] = lacc[1][0];
        SL[dcW * QM + rb + 24 + gid] = lacc[1][1];
    }
    __syncthreads();

    float inv[2][2];
#pragma unroll
    for (int rbk = 0; rbk < 2; rbk++)
#pragma unroll
        for (int h = 0; h < 2; h++) {
            const int row = rb + rbk * 16 + h * 8 + gid;
            float s = SL[row] + SL[QM + row] + SL[2 * QM + row] + SL[3 * QM + row];
            inv[rbk][h] = 1.f / s;
        }

    // ---- epilogue ----
#pragma unroll
    for (int rbk = 0; rbk < 2; rbk++) {
        const int q = q0 + rb + rbk * 16 + gid;
#pragma unroll
        for (int n = 0; n < 8; n++) {
            const int d0 = dstart + n * 8 + 2 * tig;
            size_t i0 = ((size_t)(b * NC + d0)) * NPOS + q;
            out[i0]            = o[rbk][n][0] * inv[rbk][0] + x[i0];
            out[i0 + NPOS]     = o[rbk][n][1] * inv[rbk][0] + x[i0 + NPOS];
            out[i0 + 8]        = o[rbk][n][2] * inv[rbk][1] + x[i0 + 8];
            out[i0 + NPOS + 8] = o[rbk][n][3] * inv[rbk][1] + x[i0 + NPOS + 8];
        }
    }
}

// ---------------------------------------------------------------------------
extern "C" void kernel_launch(void* const* d_in, const int* in_sizes, int n_in,
                              void* d_out, int out_size)
{
    const float* x  = (const float*)d_in[0];
    const float* w1 = (const float*)d_in[1];
    const float* w2 = (const float*)d_in[2];
    const float* w3 = (const float*)d_in[3];
    float* out = (float*)d_out;

    cudaFuncSetAttribute(proj_kernel, cudaFuncAttributeMaxDynamicSharedMemorySize,
                         PROJ_SMEM);
    cudaFuncSetAttribute(attn_kernel, cudaFuncAttributeMaxDynamicSharedMemorySize,
                         SMEM_BYTES);

    dim3 gproj(NPOS / 256, 320 / 64, NB);   // (16, 5, 4)
    proj_kernel<<<gproj, 256, PROJ_SMEM>>>(x, w1, w2, w3);

    dim3 gattn(NPOS / QM, NB);              // (32, 4)
    attn_kernel<<<gattn, THREADS, SMEM_BYTES>>>(x, out);
}

// round 16
// speedup vs baseline: 1.0154x; 1.0154x over previous
#include <cuda_runtime.h>
#include <cuda_fp16.h>
#include <cstdint>

#define NB 4
#define NC 256
#define NK 32
#define NPOS 4096
#define QM 128
#define TK 128
#define NT (NPOS / TK)    // 32
#define THREADS 512
#define LOG2E 1.4426950408889634f

// ---------------- scratch (device globals; no allocs allowed) ---------------
__device__ __align__(128) __half g_Q[(size_t)NB * NK * NPOS];   // [b][c][n]
__device__ __align__(128) __half g_K[(size_t)NB * NK * NPOS];   // [b][c][n]
__device__ __align__(128) __half g_V[(size_t)NB * NC * NPOS];   // [b][d][n]
__device__ __align__(128) float  g_M[(size_t)NB * NPOS];        // row maxes (log2 units)

// ---------------- helpers ---------------------------------------------------
__device__ __forceinline__ uint32_t s2u(const void* p) {
    uint32_t a;
    asm("{ .reg .u64 t; cvta.to.shared.u64 t, %1; cvt.u32.u64 %0, t; }"
        : "=r"(a) : "l"(p));
    return a;
}
__device__ __forceinline__ void cp16(uint32_t s, const void* g) {
    asm volatile("cp.async.cg.shared.global [%0], [%1], 16;" :: "r"(s), "l"(g));
}
#define CP_COMMIT() asm volatile("cp.async.commit_group;" ::: "memory")
#define CP_WAIT(n)  asm volatile("cp.async.wait_group %0;" :: "n"(n) : "memory")

__device__ __forceinline__ float ex2f(float x) {
    float r; asm("ex2.approx.f32 %0, %1;" : "=f"(r) : "f"(x)); return r;
}
__device__ __forceinline__ void mma16(float* c, const uint32_t* a,
                                      uint32_t b0, uint32_t b1) {
    asm volatile(
        "mma.sync.aligned.m16n8k16.row.col.f32.f16.f16.f32 "
        "{%0,%1,%2,%3}, {%4,%5,%6,%7}, {%8,%9}, {%0,%1,%2,%3};"
        : "+f"(c[0]), "+f"(c[1]), "+f"(c[2]), "+f"(c[3])
        : "r"(a[0]), "r"(a[1]), "r"(a[2]), "r"(a[3]), "r"(b0), "r"(b1));
}
__device__ __forceinline__ void mma16h(uint32_t* c, const uint32_t* a,
                                       uint32_t b0, uint32_t b1) {
    asm volatile(
        "mma.sync.aligned.m16n8k16.row.col.f16.f16.f16.f16 "
        "{%0,%1}, {%2,%3,%4,%5}, {%6,%7}, {%0,%1};"
        : "+r"(c[0]), "+r"(c[1])
        : "r"(a[0]), "r"(a[1]), "r"(a[2]), "r"(a[3]), "r"(b0), "r"(b1));
}
__device__ __forceinline__ void ldsm4(uint32_t* r, uint32_t saddr) {
    asm volatile("ldmatrix.sync.aligned.m8n8.x4.shared.b16 {%0,%1,%2,%3}, [%4];"
        : "=r"(r[0]), "=r"(r[1]), "=r"(r[2]), "=r"(r[3]) : "r"(saddr));
}
__device__ __forceinline__ void ldsm4t(uint32_t* r, uint32_t saddr) {
    asm volatile("ldmatrix.sync.aligned.m8n8.x4.trans.shared.b16 {%0,%1,%2,%3}, [%4];"
        : "=r"(r[0]), "=r"(r[1]), "=r"(r[2]), "=r"(r[3]) : "r"(saddr));
}

// ---- attn smem (halfs / bytes) ----
#define QSTR 136
#define KSTR 136
#define VSH 136
#define PSH 136
#define SM_Q 0
#define QTILEB (32 * QSTR * 2)                 // 8704
#define SM_K (SM_Q + QTILEB)                   // 8704
#define KBUFB (32 * KSTR * 2)                  // 8704
#define SM_V (SM_K + 2 * KBUFB)                // 26112
#define VBUFB (NC * VSH * 2)                   // 69632
#define SM_P (SM_V + 2 * VBUFB)                // 165376
#define SM_L (SM_P + QM * PSH * 2)             // 200192
#define SMEM_BYTES (SM_L + 4 * QM * 4)         // 202240

// ---- qkmax smem strides (c-major, 128-q tile, 256-key tile) ----
#define MQSTR 136
#define MKSTR 264
#define MTK 256
#define MNT (NPOS / MTK)   // 16

// ---- proj smem ----
#define AST 264
#define BST 264
#define PROJ_A_B (64 * AST * 2)                // 33792
#define PROJ_BBUF (32 * BST * 2)               // 16896
#define PROJ_SMEM (PROJ_A_B + 2 * PROJ_BBUF)   // 67584

// ---------------------------------------------------------------------------
// Projection fp16 GEMM. W fp32 -> fp16 converted inline into the A tile
// (no cvt_w kernel); x read fp32, converted per chunk (reg double-buffered).
// ---------------------------------------------------------------------------
__global__ __launch_bounds__(256, 2) void proj_kernel(
    const float* __restrict__ x, const float* __restrict__ w1,
    const float* __restrict__ w2, const float* __restrict__ w3)
{
    extern __shared__ __half PH[];
    const uint32_t sA = s2u(PH);
    __half* Bh = PH + PROJ_A_B / 2;

    const int n0 = blockIdx.x * 256;
    const int k0 = blockIdx.y * 64;
    const int b  = blockIdx.z;
    const int t  = threadIdx.x;
    const int wid = t >> 5, lid = t & 31;
    const int mw = wid & 3, nh = wid >> 2;
    const int gid = lid >> 2, tig = lid & 3;

    const float* xb = x + (size_t)b * NC * NPOS + n0;

    // A tile: 64 rows x 256 c, fp32 LDG -> fp16 STS (log2e on Q rows)
    {
#pragma unroll
        for (int s = 0; s < 8; s++) {
            int i = t + s * 256;
            int r = i >> 5, o = i & 31;          // row, 8-float group
            int kg = k0 + r;
            const float* wp; float sc;
            if (kg < 32)      { wp = w1 + kg * 256;        sc = LOG2E; }
            else if (kg < 64) { wp = w2 + (kg - 32) * 256; sc = 1.f; }
            else              { wp = w3 + (kg - 64) * 256; sc = 1.f; }
            float4 a0 = *(const float4*)(wp + o * 8);
            float4 a1 = *(const float4*)(wp + o * 8 + 4);
            __half2 h[4];
            h[0] = __floats2half2_rn(a0.x * sc, a0.y * sc);
            h[1] = __floats2half2_rn(a0.z * sc, a0.w * sc);
            h[2] = __floats2half2_rn(a1.x * sc, a1.y * sc);
            h[3] = __floats2half2_rn(a1.z * sc, a1.w * sc);
            *(uint4*)(PH + r * AST + o * 8) = *(uint4*)h;
        }
    }

    // prefetch B chunk 0 into registers
    float4 xv[8];
#pragma unroll
    for (int s = 0; s < 8; s++) {
        int i = t + s * 256;
        int c = i >> 6, n4 = i & 63;
        xv[s] = *(const float4*)(xb + (size_t)c * NPOS + n4 * 4);
    }

    __syncthreads();   // A tile visible

    float o[16][4];
#pragma unroll
    for (int n = 0; n < 16; n++)
#pragma unroll
        for (int c = 0; c < 4; c++) o[n][c] = 0.f;

    for (int ci = 0; ci < 8; ci++) {
        const int buf = ci & 1;
        __half* Bb = Bh + buf * (32 * BST);
#pragma unroll
        for (int s = 0; s < 8; s++) {
            int i = t + s * 256;
            int c = i >> 6, n4 = i & 63;
            __half2 h0 = __floats2half2_rn(xv[s].x, xv[s].y);
            __half2 h1 = __floats2half2_rn(xv[s].z, xv[s].w);
            *(__half2*)(Bb + c * BST + n4 * 4)     = h0;
            *(__half2*)(Bb + c * BST + n4 * 4 + 2) = h1;
        }
        __syncthreads();
        if (ci < 7) {
            const float* xc = xb + (size_t)(ci + 1) * 32 * NPOS;
#pragma unroll
            for (int s = 0; s < 8; s++) {
                int i = t + s * 256;
                int c = i >> 6, n4 = i & 63;
                xv[s] = *(const float4*)(xc + (size_t)c * NPOS + n4 * 4);
            }
        }
        const uint32_t bB = s2u(Bb);
#pragma unroll
        for (int kk2 = 0; kk2 < 2; kk2++) {
            uint32_t af[4];
            ldsm4(af, sA + ((mw * 16 + (lid & 15)) * AST +
                            ci * 32 + kk2 * 16 + ((lid >> 4) << 3)) * 2);
#pragma unroll
            for (int nb = 0; nb < 8; nb++) {
                uint32_t bf[4];
                ldsm4t(bf, bB + ((kk2 * 16 + (lid & 15)) * BST +
                                 nh * 128 + nb * 16 + ((lid >> 4) << 3)) * 2);
                mma16(o[2 * nb],     af, bf[0], bf[1]);
                mma16(o[2 * nb + 1], af, bf[2], bf[3]);
            }
        }
    }

#pragma unroll
    for (int hh = 0; hh < 2; hh++) {
        int k = k0 + mw * 16 + gid + hh * 8;
        __half* dst = (k < 32) ? g_Q + ((size_t)b * NK + k) * NPOS
                    : (k < 64) ? g_K + ((size_t)b * NK + (k - 32)) * NPOS
                               : g_V + ((size_t)b * NC + (k - 64)) * NPOS;
#pragma unroll
        for (int nb = 0; nb < 16; nb++) {
            int n = n0 + nh * 128 + nb * 8 + 2 * tig;
            *(__half2*)(dst + n) = __floats2half2_rn(o[nb][2 * hh], o[nb][2 * hh + 1]);
        }
    }
}

// ---------------------------------------------------------------------------
// Row-max pre-pass, fp16 accumulation, 256-key tiles (R14 form).
// ---------------------------------------------------------------------------
__global__ __launch_bounds__(512) void qkmax_kernel()
{
    __shared__ __align__(16) __half Qs[32 * MQSTR];
    __shared__ __align__(16) __half Ks[2 * 32 * MKSTR];
    __shared__ float Mred[4 * 128];

    const uint32_t sbQ = s2u(Qs), sbK = s2u(Ks);
    const int t   = threadIdx.x;
    const int wid = t >> 5, lid = t & 31;
    const int mg  = wid & 3, dcW = wid >> 2;
    const int rb  = mg * 32, kbase = dcW * 64;
    const int b   = blockIdx.y;
    const int q0  = blockIdx.x * 128;

    const int qc = ((lid >> 4) << 3) | (lid & 7);
    const int qq = ((lid >> 3) & 1) << 3;
    const int kc = lid & 15;
    const int kn = (lid >> 4) << 3;

    const __half* Qg = g_Q + (size_t)b * NK * NPOS + q0;
    const __half* Kg = g_K + (size_t)b * NK * NPOS;

    {
        int c = t >> 4, o = t & 15;
        cp16(sbQ + (c * MQSTR + o * 8) * 2, Qg + (size_t)c * NPOS + o * 8);
#pragma unroll
        for (int s = 0; s < 2; s++) {
            int i = t + s * 512;
            int kcc = i >> 5, ko = i & 31;
            cp16(sbK + (kcc * MKSTR + ko * 8) * 2, Kg + (size_t)kcc * NPOS + ko * 8);
        }
        CP_COMMIT();
    }

    const __half2 NEGINF = __floats2half2_rn(-65504.f, -65504.f);
    __half2 mxh[2][2];
#pragma unroll
    for (int a = 0; a < 2; a++)
#pragma unroll
        for (int h = 0; h < 2; h++) mxh[a][h] = NEGINF;

    uint32_t qf[2][2][4];
    bool qloaded = false;

    for (int j = 0; j < MNT; j++) {
        const int cur = j & 1;
        CP_WAIT(0);
        __syncthreads();
        if (!qloaded) {
            qloaded = true;
#pragma unroll
            for (int rbk = 0; rbk < 2; rbk++)
#pragma unroll
                for (int kk = 0; kk < 2; kk++)
                    ldsm4t(qf[rbk][kk],
                           sbQ + ((kk * 16 + qc) * MQSTR + rb + rbk * 16 + qq) * 2);
        }
        if (j + 1 < MNT) {
            const size_t koff = (size_t)(j + 1) * MTK;
#pragma unroll
            for (int s = 0; s < 2; s++) {
                int i = t + s * 512;
                int kcc = i >> 5, ko = i & 31;
                cp16(sbK + ((1 - cur) * 32 * MKSTR + kcc * MKSTR + ko * 8) * 2,
                     Kg + (size_t)kcc * NPOS + koff + ko * 8);
            }
            CP_COMMIT();
        }
        const uint32_t kbB = sbK + cur * 32 * (MKSTR * 2);
#pragma unroll
        for (int nbp = 0; nbp < 4; nbp++) {
            uint32_t kf[2][4];
#pragma unroll
            for (int kk = 0; kk < 2; kk++)
                ldsm4t(kf[kk],
                       kbB + ((kk * 16 + kc) * MKSTR + kbase + nbp * 16 + kn) * 2);
#pragma unroll
            for (int rbk = 0; rbk < 2; rbk++) {
                uint32_t c0[2] = {0u, 0u}, c1[2] = {0u, 0u};
#pragma unroll
                for (int kk = 0; kk < 2; kk++) {
                    mma16h(c0, qf[rbk][kk], kf[kk][0], kf[kk][1]);
                    mma16h(c1, qf[rbk][kk], kf[kk][2], kf[kk][3]);
                }
                __half2 h0 = __hmax2(*(__half2*)&c0[0], *(__half2*)&c1[0]);
                __half2 h1 = __hmax2(*(__half2*)&c0[1], *(__half2*)&c1[1]);
                mxh[rbk][0] = __hmax2(mxh[rbk][0], h0);
                mxh[rbk][1] = __hmax2(mxh[rbk][1], h1);
            }
        }
    }

    const int gid = lid >> 2, tig = lid & 3;
    float mx0[2], mx1[2];
#pragma unroll
    for (int rbk = 0; rbk < 2; rbk++) {
        mx0[rbk] = fmaxf(__low2float(mxh[rbk][0]), __high2float(mxh[rbk][0]));
        mx1[rbk] = fmaxf(__low2float(mxh[rbk][1]), __high2float(mxh[rbk][1]));
        mx0[rbk] = fmaxf(mx0[rbk], __shfl_xor_sync(0xffffffffu, mx0[rbk], 1));
        mx0[rbk] = fmaxf(mx0[rbk], __shfl_xor_sync(0xffffffffu, mx0[rbk], 2));
        mx1[rbk] = fmaxf(mx1[rbk], __shfl_xor_sync(0xffffffffu, mx1[rbk], 1));
        mx1[rbk] = fmaxf(mx1[rbk], __shfl_xor_sync(0xffffffffu, mx1[rbk], 2));
    }
    if (tig == 0) {
        Mred[dcW * 128 + rb + gid]      = mx0[0];
        Mred[dcW * 128 + rb + 8 + gid]  = mx1[0];
        Mred[dcW * 128 + rb + 16 + gid] = mx0[1];
        Mred[dcW * 128 + rb + 24 + gid] = mx1[1];
    }
    __syncthreads();
    if (t < 128) {
        float m = fmaxf(fmaxf(Mred[t], Mred[128 + t]),
                        fmaxf(Mred[256 + t], Mred[384 + t]));
        g_M[(size_t)b * NPOS + q0 + t] = m;
    }
}

// ---------------------------------------------------------------------------
// fp16 flash attention (R14 form: mg = wid>>2 SMSP-spanning groups).
// ---------------------------------------------------------------------------
__global__ __launch_bounds__(THREADS) void attn_kernel(
    const float* __restrict__ x, float* __restrict__ out)
{
    extern __shared__ __align__(16) char sm[];
    const uint32_t sb = s2u(sm);
    __half* Ps = (__half*)(sm + SM_P);
    float* SL  = (float*)(sm + SM_L);

    const int t   = threadIdx.x;
    const int wid = t >> 5, lid = t & 31;
    const int gid = lid >> 2, tig = lid & 3;
    const int mg  = wid >> 2, dcW = wid & 3;
    const int rb  = mg * 32;
    const int kbase  = dcW * 32;
    const int dstart = dcW * 64;
    const int b  = blockIdx.y;
    const int q0 = blockIdx.x * QM;

    const int qc = ((lid >> 4) << 3) | (lid & 7);
    const int qq = ((lid >> 3) & 1) << 3;
    const int kc = lid & 15;
    const int kn = (lid >> 4) << 3;
    const int arow  = lid & 15;
    const int acolh = (lid >> 4) << 3;
    const int brow  = ((lid >> 4) << 3) | (lid & 7);
    const int bcolh = ((lid >> 3) & 1) << 3;

    const __half* Qg = g_Q + (size_t)b * NK * NPOS + q0;
    const __half* Kg = g_K + (size_t)b * NK * NPOS;
    const __half* Vg = g_V + (size_t)b * NC * NPOS;

    const float* Mg = g_M + (size_t)b * NPOS + q0;
    float m0[2], m1[2];
    m0[0] = Mg[rb + gid];      m1[0] = Mg[rb + 8 + gid];
    m0[1] = Mg[rb + 16 + gid]; m1[1] = Mg[rb + 24 + gid];

    {
        int c = t >> 4, o = t & 15;
        cp16(sb + SM_Q + (c * QSTR + o * 8) * 2, Qg + (size_t)c * NPOS + o * 8);
        cp16(sb + SM_K + (c * KSTR + o * 8) * 2, Kg + (size_t)c * NPOS + o * 8);
#pragma unroll
        for (int s = 0; s < 8; s++) {
            int i = t + s * THREADS;
            int d = i >> 4, k4 = i & 15;
            cp16(sb + SM_V + (d * VSH + k4 * 8) * 2, Vg + (size_t)d * NPOS + k4 * 8);
        }
        CP_COMMIT();
    }

    float o[2][8][4];
#pragma unroll
    for (int r = 0; r < 2; r++)
#pragma unroll
        for (int n = 0; n < 8; n++)
#pragma unroll
            for (int c = 0; c < 4; c++) o[r][n][c] = 0.f;

    float lacc[2][2] = {{0.f, 0.f}, {0.f, 0.f}};
    uint32_t qf[2][2][4];
    bool qloaded = false;

    for (int j = 0; j < NT; j++) {
        const int cur = j & 1;
        CP_WAIT(0);
        __syncthreads();

        if (!qloaded) {
            qloaded = true;
#pragma unroll
            for (int rbk = 0; rbk < 2; rbk++)
#pragma unroll
                for (int kk = 0; kk < 2; kk++)
                    ldsm4t(qf[rbk][kk],
                           sb + SM_Q + ((kk * 16 + qc) * QSTR + rb + rbk * 16 + qq) * 2);
        }

        if (j + 1 < NT) {
            const size_t koff = (size_t)(j + 1) * TK;
            int c = t >> 4, o2 = t & 15;
            cp16(sb + SM_K + ((1 - cur) * 32 * KSTR + c * KSTR + o2 * 8) * 2,
                 Kg + (size_t)c * NPOS + koff + o2 * 8);
#pragma unroll
            for (int s = 0; s < 8; s++) {
                int i = t + s * THREADS;
                int d = i >> 4, k4 = i & 15;
                cp16(sb + SM_V + (1 - cur) * VBUFB + (d * VSH + k4 * 8) * 2,
                     Vg + (size_t)d * NPOS + koff + k4 * 8);
            }
            CP_COMMIT();
        }

        // ---- phase A: S = Q K^T, e = 2^(s-m), P -> smem ----
        {
            const uint32_t kbB = sb + SM_K + cur * KBUFB;
#pragma unroll
            for (int nbp = 0; nbp < 2; nbp++) {
                uint32_t kf[2][4];
#pragma unroll
                for (int kk = 0; kk < 2; kk++)
                    ldsm4t(kf[kk],
                           kbB + ((kk * 16 + kc) * KSTR + kbase + nbp * 16 + kn) * 2);
#pragma unroll
                for (int rbk = 0; rbk < 2; rbk++) {
                    float s4[2][4] = {{0.f,0.f,0.f,0.f},{0.f,0.f,0.f,0.f}};
#pragma unroll
                    for (int kk = 0; kk < 2; kk++) {
                        mma16(s4[0], qf[rbk][kk], kf[kk][0], kf[kk][1]);
                        mma16(s4[1], qf[rbk][kk], kf[kk][2], kf[kk][3]);
                    }
                    const int q = rb + rbk * 16 + gid;
#pragma unroll
                    for (int nb2 = 0; nb2 < 2; nb2++) {
                        float e0 = ex2f(s4[nb2][0] - m0[rbk]);
                        float e1 = ex2f(s4[nb2][1] - m0[rbk]);
                        float e2 = ex2f(s4[nb2][2] - m1[rbk]);
                        float e3 = ex2f(s4[nb2][3] - m1[rbk]);
                        lacc[rbk][0] += e0 + e1;
                        lacc[rbk][1] += e2 + e3;
                        const int col = kbase + nbp * 16 + nb2 * 8 + 2 * tig;
                        *(__half2*)&Ps[q * PSH + col]       = __floats2half2_rn(e0, e1);
                        *(__half2*)&Ps[(q + 8) * PSH + col] = __floats2half2_rn(e2, e3);
                    }
                }
            }
        }
        asm volatile("bar.sync %0, 128;" :: "r"(mg + 1) : "memory");

        // ---- phase B: O += P @ V ----
        {
            const uint32_t vbB = sb + SM_V + cur * VBUFB;
#pragma unroll
            for (int kk = 0; kk < 8; kk++) {
                uint32_t pf[2][4];
#pragma unroll
                for (int rbk = 0; rbk < 2; rbk++)
                    ldsm4(pf[rbk],
                          sb + SM_P + ((rb + rbk * 16 + arow) * PSH + kk * 16 + acolh) * 2);
#pragma unroll
                for (int dp = 0; dp < 4; dp++) {
                    uint32_t vf[4];
                    ldsm4(vf, vbB + ((dstart + dp * 16 + brow) * VSH + kk * 16 + bcolh) * 2);
                    mma16(o[0][2 * dp],     pf[0], vf[0], vf[1]);
                    mma16(o[0][2 * dp + 1], pf[0], vf[2], vf[3]);
                    mma16(o[1][2 * dp],     pf[1], vf[0], vf[1]);
                    mma16(o[1][2 * dp + 1], pf[1], vf[2], vf[3]);
                }
            }
        }
    }

    // ---- denominators ----
#pragma unroll
    for (int rbk = 0; rbk < 2; rbk++)
#pragma unroll
        for (int h = 0; h < 2; h++) {
            float v = lacc[rbk][h];
            v += __shfl_xor_sync(0xffffffffu, v, 1);
            v += __shfl_xor_sync(0xffffffffu, v, 2);
            lacc[rbk][h] = v;
        }
    if (tig == 0) {
        SL[dcW * QM + rb + gid]      = lacc[0][0];
        SL[dcW * QM + rb + 8 + gid]  = lacc[0][1];
        SL[dcW * QM + rb + 16 + gid] = lacc[1][0];
        SL[dcW * QM + rb + 24 + gid] = lacc[1][1];
    }
    __syncthreads();

    float inv[2][2];
#pragma unroll
    for (int rbk = 0; rbk < 2; rbk++)
#pragma unroll
        for (int h = 0; h < 2; h++) {
            const int row = rb + rbk * 16 + h * 8 + gid;
            float s = SL[row] + SL[QM + row] + SL[2 * QM + row] + SL[3 * QM + row];
            inv[rbk][h] = 1.f / s;
        }

    // ---- epilogue ----
#pragma unroll
    for (int rbk = 0; rbk < 2; rbk++) {
        const int q = q0 + rb + rbk * 16 + gid;
#pragma unroll
        for (int n = 0; n < 8; n++) {
            const int d0 = dstart + n * 8 + 2 * tig;
            size_t i0 = ((size_t)(b * NC + d0)) * NPOS + q;
            out[i0]            = o[rbk][n][0] * inv[rbk][0] + x[i0];
            out[i0 + NPOS]     = o[rbk][n][1] * inv[rbk][0] + x[i0 + NPOS];
            out[i0 + 8]        = o[rbk][n][2] * inv[rbk][1] + x[i0 + 8];
            out[i0 + NPOS + 8] = o[rbk][n][3] * inv[rbk][1] + x[i0 + NPOS + 8];
        }
    }
}

// ---------------------------------------------------------------------------
extern "C" void kernel_launch(void* const* d_in, const int* in_sizes, int n_in,
                              void* d_out, int out_size)
{
    const float* x  = (const float*)d_in[0];
    const float* w1 = (const float*)d_in[1];
    const float* w2 = (const float*)d_in[2];
    const float* w3 = (const float*)d_in[3];
    float* out = (float*)d_out;

    cudaFuncSetAttribute(proj_kernel, cudaFuncAttributeMaxDynamicSharedMemorySize,
                         PROJ_SMEM);
    cudaFuncSetAttribute(attn_kernel, cudaFuncAttributeMaxDynamicSharedMemorySize,
                         SMEM_BYTES);

    dim3 gproj(NPOS / 256, 320 / 64, NB);   // (16, 5, 4)
    proj_kernel<<<gproj, 256, PROJ_SMEM>>>(x, w1, w2, w3);

    dim3 gqk(NPOS / 128, NB);               // (32, 4)
    qkmax_kernel<<<gqk, 512>>>();

    dim3 gattn(NPOS / QM, NB);              // (32, 4)
    attn_kernel<<<gattn, THREADS, SMEM_BYTES>>>(x, out);
}

// round 17
// speedup vs baseline: 1.0356x; 1.0198x over previous
#include <cuda_runtime.h>
#include <cuda_fp16.h>
#include <cstdint>

#define NB 4
#define NC 256
#define NK 32
#define NPOS 4096
#define QM 128
#define TK 128
#define NT (NPOS / TK)    // 32
#define THREADS 512
#define LOG2E 1.4426950408889634f

// ---------------- scratch (device globals; no allocs allowed) ---------------
__device__ __align__(128) __half g_Q[(size_t)NB * NK * NPOS];   // [b][c][n]
__device__ __align__(128) __half g_K[(size_t)NB * NK * NPOS];   // [b][c][n]
__device__ __align__(128) __half g_V[(size_t)NB * NC * NPOS];   // [b][d][n]
__device__ __align__(128) float  g_M[(size_t)NB * NPOS];        // row maxes (log2 units)

// ---------------- helpers ---------------------------------------------------
__device__ __forceinline__ uint32_t s2u(const void* p) {
    uint32_t a;
    asm("{ .reg .u64 t; cvta.to.shared.u64 t, %1; cvt.u32.u64 %0, t; }"
        : "=r"(a) : "l"(p));
    return a;
}
__device__ __forceinline__ void cp16(uint32_t s, const void* g) {
    asm volatile("cp.async.cg.shared.global [%0], [%1], 16;" :: "r"(s), "l"(g));
}
#define CP_COMMIT() asm volatile("cp.async.commit_group;" ::: "memory")
#define CP_WAIT(n)  asm volatile("cp.async.wait_group %0;" :: "n"(n) : "memory")

__device__ __forceinline__ float ex2f(float x) {
    float r; asm("ex2.approx.f32 %0, %1;" : "=f"(r) : "f"(x)); return r;
}
__device__ __forceinline__ void mma16(float* c, const uint32_t* a,
                                      uint32_t b0, uint32_t b1) {
    asm volatile(
        "mma.sync.aligned.m16n8k16.row.col.f32.f16.f16.f32 "
        "{%0,%1,%2,%3}, {%4,%5,%6,%7}, {%8,%9}, {%0,%1,%2,%3};"
        : "+f"(c[0]), "+f"(c[1]), "+f"(c[2]), "+f"(c[3])
        : "r"(a[0]), "r"(a[1]), "r"(a[2]), "r"(a[3]), "r"(b0), "r"(b1));
}
__device__ __forceinline__ void mma16h(uint32_t* c, const uint32_t* a,
                                       uint32_t b0, uint32_t b1) {
    asm volatile(
        "mma.sync.aligned.m16n8k16.row.col.f16.f16.f16.f16 "
        "{%0,%1}, {%2,%3,%4,%5}, {%6,%7}, {%0,%1};"
        : "+r"(c[0]), "+r"(c[1])
        : "r"(a[0]), "r"(a[1]), "r"(a[2]), "r"(a[3]), "r"(b0), "r"(b1));
}
__device__ __forceinline__ void ldsm4(uint32_t* r, uint32_t saddr) {
    asm volatile("ldmatrix.sync.aligned.m8n8.x4.shared.b16 {%0,%1,%2,%3}, [%4];"
        : "=r"(r[0]), "=r"(r[1]), "=r"(r[2]), "=r"(r[3]) : "r"(saddr));
}
__device__ __forceinline__ void ldsm4t(uint32_t* r, uint32_t saddr) {
    asm volatile("ldmatrix.sync.aligned.m8n8.x4.trans.shared.b16 {%0,%1,%2,%3}, [%4];"
        : "=r"(r[0]), "=r"(r[1]), "=r"(r[2]), "=r"(r[3]) : "r"(saddr));
}

// ---- attn smem (halfs / bytes) ----
#define QSTR 136
#define KSTR 136
#define VSH 136
#define PSH 136
#define SM_Q 0
#define QTILEB (32 * QSTR * 2)                 // 8704
#define SM_K (SM_Q + QTILEB)                   // 8704
#define KBUFB (32 * KSTR * 2)                  // 8704
#define SM_V (SM_K + 2 * KBUFB)                // 26112
#define VBUFB (NC * VSH * 2)                   // 69632
#define SM_P (SM_V + 2 * VBUFB)                // 165376
#define SM_L (SM_P + QM * PSH * 2)             // 200192
#define SMEM_BYTES (SM_L + 4 * QM * 4)         // 202240

// ---- qkmax smem strides (c-major, 128-q tile, 256-key tile) ----
#define MQSTR 136
#define MKSTR 264
#define MTK 256
#define MNT (NPOS / MTK)   // 16

// ---- proj smem (n-tile 128, k-tile 64) ----
#define AST 264
#define BST 136
#define PROJ_A_B (64 * AST * 2)                // 33792
#define PROJ_BBUF (32 * BST * 2)               // 8704
#define PROJ_SMEM (PROJ_A_B + 2 * PROJ_BBUF)   // 51200

// ---------------------------------------------------------------------------
// Projection fp16 GEMM, retiled: CTA = 64k x 128n, 256 thr, 3 CTAs/SM.
// W fp32 -> fp16 inline into A tile; x fp32 LDG -> reg -> fp16 STS per chunk.
// 8 warps: mw = wid&3 (m16 block), nh = wid>>2 (64 n).
// ---------------------------------------------------------------------------
__global__ __launch_bounds__(256, 3) void proj_kernel(
    const float* __restrict__ x, const float* __restrict__ w1,
    const float* __restrict__ w2, const float* __restrict__ w3)
{
    extern __shared__ __half PH[];
    const uint32_t sA = s2u(PH);
    __half* Bh = PH + PROJ_A_B / 2;

    const int n0 = blockIdx.x * 128;
    const int k0 = blockIdx.y * 64;
    const int b  = blockIdx.z;
    const int t  = threadIdx.x;
    const int wid = t >> 5, lid = t & 31;
    const int mw = wid & 3, nh = wid >> 2;
    const int gid = lid >> 2, tig = lid & 3;

    const float* xb = x + (size_t)b * NC * NPOS + n0;

    // A tile: 64 rows x 256 c, fp32 LDG -> fp16 STS (log2e on Q rows)
    {
#pragma unroll
        for (int s = 0; s < 8; s++) {
            int i = t + s * 256;
            int r = i >> 5, o = i & 31;
            int kg = k0 + r;
            const float* wp; float sc;
            if (kg < 32)      { wp = w1 + kg * 256;        sc = LOG2E; }
            else if (kg < 64) { wp = w2 + (kg - 32) * 256; sc = 1.f; }
            else              { wp = w3 + (kg - 64) * 256; sc = 1.f; }
            float4 a0 = *(const float4*)(wp + o * 8);
            float4 a1 = *(const float4*)(wp + o * 8 + 4);
            __half2 h[4];
            h[0] = __floats2half2_rn(a0.x * sc, a0.y * sc);
            h[1] = __floats2half2_rn(a0.z * sc, a0.w * sc);
            h[2] = __floats2half2_rn(a1.x * sc, a1.y * sc);
            h[3] = __floats2half2_rn(a1.z * sc, a1.w * sc);
            *(uint4*)(PH + r * AST + o * 8) = *(uint4*)h;
        }
    }

    // prefetch B chunk 0: 32c x 128n = 1024 float4, 4 per thread
    float4 xv[4];
#pragma unroll
    for (int s = 0; s < 4; s++) {
        int i = t + s * 256;
        int c = i >> 5, n4 = i & 31;
        xv[s] = *(const float4*)(xb + (size_t)c * NPOS + n4 * 4);
    }

    __syncthreads();   // A tile visible

    float o[8][4];
#pragma unroll
    for (int n = 0; n < 8; n++)
#pragma unroll
        for (int c = 0; c < 4; c++) o[n][c] = 0.f;

    for (int ci = 0; ci < 8; ci++) {
        const int buf = ci & 1;
        __half* Bb = Bh + buf * (32 * BST);
#pragma unroll
        for (int s = 0; s < 4; s++) {
            int i = t + s * 256;
            int c = i >> 5, n4 = i & 31;
            __half2 h0 = __floats2half2_rn(xv[s].x, xv[s].y);
            __half2 h1 = __floats2half2_rn(xv[s].z, xv[s].w);
            *(__half2*)(Bb + c * BST + n4 * 4)     = h0;
            *(__half2*)(Bb + c * BST + n4 * 4 + 2) = h1;
        }
        __syncthreads();
        if (ci < 7) {
            const float* xc = xb + (size_t)(ci + 1) * 32 * NPOS;
#pragma unroll
            for (int s = 0; s < 4; s++) {
                int i = t + s * 256;
                int c = i >> 5, n4 = i & 31;
                xv[s] = *(const float4*)(xc + (size_t)c * NPOS + n4 * 4);
            }
        }
        const uint32_t bB = s2u(Bb);
#pragma unroll
        for (int kk2 = 0; kk2 < 2; kk2++) {
            uint32_t af[4];
            ldsm4(af, sA + ((mw * 16 + (lid & 15)) * AST +
                            ci * 32 + kk2 * 16 + ((lid >> 4) << 3)) * 2);
#pragma unroll
            for (int nb = 0; nb < 4; nb++) {
                uint32_t bf[4];
                ldsm4t(bf, bB + ((kk2 * 16 + (lid & 15)) * BST +
                                 nh * 64 + nb * 16 + ((lid >> 4) << 3)) * 2);
                mma16(o[2 * nb],     af, bf[0], bf[1]);
                mma16(o[2 * nb + 1], af, bf[2], bf[3]);
            }
        }
    }

    // epilogue: natural [k][n] half2 stores
#pragma unroll
    for (int hh = 0; hh < 2; hh++) {
        int k = k0 + mw * 16 + gid + hh * 8;
        __half* dst = (k < 32) ? g_Q + ((size_t)b * NK + k) * NPOS
                    : (k < 64) ? g_K + ((size_t)b * NK + (k - 32)) * NPOS
                               : g_V + ((size_t)b * NC + (k - 64)) * NPOS;
#pragma unroll
        for (int nb = 0; nb < 8; nb++) {
            int n = n0 + nh * 64 + nb * 8 + 2 * tig;
            *(__half2*)(dst + n) = __floats2half2_rn(o[nb][2 * hh], o[nb][2 * hh + 1]);
        }
    }
}

// ---------------------------------------------------------------------------
// Row-max pre-pass, fp16 accumulation, 256-key tiles (unchanged).
// ---------------------------------------------------------------------------
__global__ __launch_bounds__(512) void qkmax_kernel()
{
    __shared__ __align__(16) __half Qs[32 * MQSTR];
    __shared__ __align__(16) __half Ks[2 * 32 * MKSTR];
    __shared__ float Mred[4 * 128];

    const uint32_t sbQ = s2u(Qs), sbK = s2u(Ks);
    const int t   = threadIdx.x;
    const int wid = t >> 5, lid = t & 31;
    const int mg  = wid & 3, dcW = wid >> 2;
    const int rb  = mg * 32, kbase = dcW * 64;
    const int b   = blockIdx.y;
    const int q0  = blockIdx.x * 128;

    const int qc = ((lid >> 4) << 3) | (lid & 7);
    const int qq = ((lid >> 3) & 1) << 3;
    const int kc = lid & 15;
    const int kn = (lid >> 4) << 3;

    const __half* Qg = g_Q + (size_t)b * NK * NPOS + q0;
    const __half* Kg = g_K + (size_t)b * NK * NPOS;

    {
        int c = t >> 4, o = t & 15;
        cp16(sbQ + (c * MQSTR + o * 8) * 2, Qg + (size_t)c * NPOS + o * 8);
#pragma unroll
        for (int s = 0; s < 2; s++) {
            int i = t + s * 512;
            int kcc = i >> 5, ko = i & 31;
            cp16(sbK + (kcc * MKSTR + ko * 8) * 2, Kg + (size_t)kcc * NPOS + ko * 8);
        }
        CP_COMMIT();
    }

    const __half2 NEGINF = __floats2half2_rn(-65504.f, -65504.f);
    __half2 mxh[2][2];
#pragma unroll
    for (int a = 0; a < 2; a++)
#pragma unroll
        for (int h = 0; h < 2; h++) mxh[a][h] = NEGINF;

    uint32_t qf[2][2][4];
    bool qloaded = false;

    for (int j = 0; j < MNT; j++) {
        const int cur = j & 1;
        CP_WAIT(0);
        __syncthreads();
        if (!qloaded) {
            qloaded = true;
#pragma unroll
            for (int rbk = 0; rbk < 2; rbk++)
#pragma unroll
                for (int kk = 0; kk < 2; kk++)
                    ldsm4t(qf[rbk][kk],
                           sbQ + ((kk * 16 + qc) * MQSTR + rb + rbk * 16 + qq) * 2);
        }
        if (j + 1 < MNT) {
            const size_t koff = (size_t)(j + 1) * MTK;
#pragma unroll
            for (int s = 0; s < 2; s++) {
                int i = t + s * 512;
                int kcc = i >> 5, ko = i & 31;
                cp16(sbK + ((1 - cur) * 32 * MKSTR + kcc * MKSTR + ko * 8) * 2,
                     Kg + (size_t)kcc * NPOS + koff + ko * 8);
            }
            CP_COMMIT();
        }
        const uint32_t kbB = sbK + cur * 32 * (MKSTR * 2);
#pragma unroll
        for (int nbp = 0; nbp < 4; nbp++) {
            uint32_t kf[2][4];
#pragma unroll
            for (int kk = 0; kk < 2; kk++)
                ldsm4t(kf[kk],
                       kbB + ((kk * 16 + kc) * MKSTR + kbase + nbp * 16 + kn) * 2);
#pragma unroll
            for (int rbk = 0; rbk < 2; rbk++) {
                uint32_t c0[2] = {0u, 0u}, c1[2] = {0u, 0u};
#pragma unroll
                for (int kk = 0; kk < 2; kk++) {
                    mma16h(c0, qf[rbk][kk], kf[kk][0], kf[kk][1]);
                    mma16h(c1, qf[rbk][kk], kf[kk][2], kf[kk][3]);
                }
                __half2 h0 = __hmax2(*(__half2*)&c0[0], *(__half2*)&c1[0]);
                __half2 h1 = __hmax2(*(__half2*)&c0[1], *(__half2*)&c1[1]);
                mxh[rbk][0] = __hmax2(mxh[rbk][0], h0);
                mxh[rbk][1] = __hmax2(mxh[rbk][1], h1);
            }
        }
    }

    const int gid = lid >> 2, tig = lid & 3;
    float mx0[2], mx1[2];
#pragma unroll
    for (int rbk = 0; rbk < 2; rbk++) {
        mx0[rbk] = fmaxf(__low2float(mxh[rbk][0]), __high2float(mxh[rbk][0]));
        mx1[rbk] = fmaxf(__low2float(mxh[rbk][1]), __high2float(mxh[rbk][1]));
        mx0[rbk] = fmaxf(mx0[rbk], __shfl_xor_sync(0xffffffffu, mx0[rbk], 1));
        mx0[rbk] = fmaxf(mx0[rbk], __shfl_xor_sync(0xffffffffu, mx0[rbk], 2));
        mx1[rbk] = fmaxf(mx1[rbk], __shfl_xor_sync(0xffffffffu, mx1[rbk], 1));
        mx1[rbk] = fmaxf(mx1[rbk], __shfl_xor_sync(0xffffffffu, mx1[rbk], 2));
    }
    if (tig == 0) {
        Mred[dcW * 128 + rb + gid]      = mx0[0];
        Mred[dcW * 128 + rb + 8 + gid]  = mx1[0];
        Mred[dcW * 128 + rb + 16 + gid] = mx0[1];
        Mred[dcW * 128 + rb + 24 + gid] = mx1[1];
    }
    __syncthreads();
    if (t < 128) {
        float m = fmaxf(fmaxf(Mred[t], Mred[128 + t]),
                        fmaxf(Mred[256 + t], Mred[384 + t]));
        g_M[(size_t)b * NPOS + q0 + t] = m;
    }
}

// ---------------------------------------------------------------------------
// fp16 flash attention (R14 form, unchanged).
// ---------------------------------------------------------------------------
__global__ __launch_bounds__(THREADS) void attn_kernel(
    const float* __restrict__ x, float* __restrict__ out)
{
    extern __shared__ __align__(16) char sm[];
    const uint32_t sb = s2u(sm);
    __half* Ps = (__half*)(sm + SM_P);
    float* SL  = (float*)(sm + SM_L);

    const int t   = threadIdx.x;
    const int wid = t >> 5, lid = t & 31;
    const int gid = lid >> 2, tig = lid & 3;
    const int mg  = wid >> 2, dcW = wid & 3;
    const int rb  = mg * 32;
    const int kbase  = dcW * 32;
    const int dstart = dcW * 64;
    const int b  = blockIdx.y;
    const int q0 = blockIdx.x * QM;

    const int qc = ((lid >> 4) << 3) | (lid & 7);
    const int qq = ((lid >> 3) & 1) << 3;
    const int kc = lid & 15;
    const int kn = (lid >> 4) << 3;
    const int arow  = lid & 15;
    const int acolh = (lid >> 4) << 3;
    const int brow  = ((lid >> 4) << 3) | (lid & 7);
    const int bcolh = ((lid >> 3) & 1) << 3;

    const __half* Qg = g_Q + (size_t)b * NK * NPOS + q0;
    const __half* Kg = g_K + (size_t)b * NK * NPOS;
    const __half* Vg = g_V + (size_t)b * NC * NPOS;

    const float* Mg = g_M + (size_t)b * NPOS + q0;
    float m0[2], m1[2];
    m0[0] = Mg[rb + gid];      m1[0] = Mg[rb + 8 + gid];
    m0[1] = Mg[rb + 16 + gid]; m1[1] = Mg[rb + 24 + gid];

    {
        int c = t >> 4, o = t & 15;
        cp16(sb + SM_Q + (c * QSTR + o * 8) * 2, Qg + (size_t)c * NPOS + o * 8);
        cp16(sb + SM_K + (c * KSTR + o * 8) * 2, Kg + (size_t)c * NPOS + o * 8);
#pragma unroll
        for (int s = 0; s < 8; s++) {
            int i = t + s * THREADS;
            int d = i >> 4, k4 = i & 15;
            cp16(sb + SM_V + (d * VSH + k4 * 8) * 2, Vg + (size_t)d * NPOS + k4 * 8);
        }
        CP_COMMIT();
    }

    float o[2][8][4];
#pragma unroll
    for (int r = 0; r < 2; r++)
#pragma unroll
        for (int n = 0; n < 8; n++)
#pragma unroll
            for (int c = 0; c < 4; c++) o[r][n][c] = 0.f;

    float lacc[2][2] = {{0.f, 0.f}, {0.f, 0.f}};
    uint32_t qf[2][2][4];
    bool qloaded = false;

    for (int j = 0; j < NT; j++) {
        const int cur = j & 1;
        CP_WAIT(0);
        __syncthreads();

        if (!qloaded) {
            qloaded = true;
#pragma unroll
            for (int rbk = 0; rbk < 2; rbk++)
#pragma unroll
                for (int kk = 0; kk < 2; kk++)
                    ldsm4t(qf[rbk][kk],
                           sb + SM_Q + ((kk * 16 + qc) * QSTR + rb + rbk * 16 + qq) * 2);
        }

        if (j + 1 < NT) {
            const size_t koff = (size_t)(j + 1) * TK;
            int c = t >> 4, o2 = t & 15;
            cp16(sb + SM_K + ((1 - cur) * 32 * KSTR + c * KSTR + o2 * 8) * 2,
                 Kg + (size_t)c * NPOS + koff + o2 * 8);
#pragma unroll
            for (int s = 0; s < 8; s++) {
                int i = t + s * THREADS;
                int d = i >> 4, k4 = i & 15;
                cp16(sb + SM_V + (1 - cur) * VBUFB + (d * VSH + k4 * 8) * 2,
                     Vg + (size_t)d * NPOS + koff + k4 * 8);
            }
            CP_COMMIT();
        }

        // ---- phase A: S = Q K^T, e = 2^(s-m), P -> smem ----
        {
            const uint32_t kbB = sb + SM_K + cur * KBUFB;
#pragma unroll
            for (int nbp = 0; nbp < 2; nbp++) {
                uint32_t kf[2][4];
#pragma unroll
                for (int kk = 0; kk < 2; kk++)
                    ldsm4t(kf[kk],
                           kbB + ((kk * 16 + kc) * KSTR + kbase + nbp * 16 + kn) * 2);
#pragma unroll
                for (int rbk = 0; rbk < 2; rbk++) {
                    float s4[2][4] = {{0.f,0.f,0.f,0.f},{0.f,0.f,0.f,0.f}};
#pragma unroll
                    for (int kk = 0; kk < 2; kk++) {
                        mma16(s4[0], qf[rbk][kk], kf[kk][0], kf[kk][1]);
                        mma16(s4[1], qf[rbk][kk], kf[kk][2], kf[kk][3]);
                    }
                    const int q = rb + rbk * 16 + gid;
#pragma unroll
                    for (int nb2 = 0; nb2 < 2; nb2++) {
                        float e0 = ex2f(s4[nb2][0] - m0[rbk]);
                        float e1 = ex2f(s4[nb2][1] - m0[rbk]);
                        float e2 = ex2f(s4[nb2][2] - m1[rbk]);
                        float e3 = ex2f(s4[nb2][3] - m1[rbk]);
                        lacc[rbk][0] += e0 + e1;
                        lacc[rbk][1] += e2 + e3;
                        const int col = kbase + nbp * 16 + nb2 * 8 + 2 * tig;
                        *(__half2*)&Ps[q * PSH + col]       = __floats2half2_rn(e0, e1);
                        *(__half2*)&Ps[(q + 8) * PSH + col] = __floats2half2_rn(e2, e3);
                    }
                }
            }
        }
        asm volatile("bar.sync %0, 128;" :: "r"(mg + 1) : "memory");

        // ---- phase B: O += P @ V ----
        {
            const uint32_t vbB = sb + SM_V + cur * VBUFB;
#pragma unroll
            for (int kk = 0; kk < 8; kk++) {
                uint32_t pf[2][4];
#pragma unroll
                for (int rbk = 0; rbk < 2; rbk++)
                    ldsm4(pf[rbk],
                          sb + SM_P + ((rb + rbk * 16 + arow) * PSH + kk * 16 + acolh) * 2);
#pragma unroll
                for (int dp = 0; dp < 4; dp++) {
                    uint32_t vf[4];
                    ldsm4(vf, vbB + ((dstart + dp * 16 + brow) * VSH + kk * 16 + bcolh) * 2);
                    mma16(o[0][2 * dp],     pf[0], vf[0], vf[1]);
                    mma16(o[0][2 * dp + 1], pf[0], vf[2], vf[3]);
                    mma16(o[1][2 * dp],     pf[1], vf[0], vf[1]);
                    mma16(o[1][2 * dp + 1], pf[1], vf[2], vf[3]);
                }
            }
        }
    }

    // ---- denominators ----
#pragma unroll
    for (int rbk = 0; rbk < 2; rbk++)
#pragma unroll
        for (int h = 0; h < 2; h++) {
            float v = lacc[rbk][h];
            v += __shfl_xor_sync(0xffffffffu, v, 1);
            v += __shfl_xor_sync(0xffffffffu, v, 2);
            lacc[rbk][h] = v;
        }
    if (tig == 0) {
        SL[dcW * QM + rb + gid]      = lacc[0][0];
        SL[dcW * QM + rb + 8 + gid]  = lacc[0][1];
        SL[dcW * QM + rb + 16 + gid] = lacc[1][0];
        SL[dcW * QM + rb + 24 + gid] = lacc[1][1];
    }
    __syncthreads();

    float inv[2][2];
#pragma unroll
    for (int rbk = 0; rbk < 2; rbk++)
#pragma unroll
        for (int h = 0; h < 2; h++) {
            const int row = rb + rbk * 16 + h * 8 + gid;
            float s = SL[row] + SL[QM + row] + SL[2 * QM + row] + SL[3 * QM + row];
            inv[rbk][h] = 1.f / s;
        }

    // ---- epilogue ----
#pragma unroll
    for (int rbk = 0; rbk < 2; rbk++) {
        const int q = q0 + rb + rbk * 16 + gid;
#pragma unroll
        for (int n = 0; n < 8; n++) {
            const int d0 = dstart + n * 8 + 2 * tig;
            size_t i0 = ((size_t)(b * NC + d0)) * NPOS + q;
            out[i0]            = o[rbk][n][0] * inv[rbk][0] + x[i0];
            out[i0 + NPOS]     = o[rbk][n][1] * inv[rbk][0] + x[i0 + NPOS];
            out[i0 + 8]        = o[rbk][n][2] * inv[rbk][1] + x[i0 + 8];
            out[i0 + NPOS + 8] = o[rbk][n][3] * inv[rbk][1] + x[i0 + NPOS + 8];
        }
    }
}

// ---------------------------------------------------------------------------
extern "C" void kernel_launch(void* const* d_in, const int* in_sizes, int n_in,
                              void* d_out, int out_size)
{
    const float* x  = (const float*)d_in[0];
    const float* w1 = (const float*)d_in[1];
    const float* w2 = (const float*)d_in[2];
    const float* w3 = (const float*)d_in[3];
    float* out = (float*)d_out;

    cudaFuncSetAttribute(proj_kernel, cudaFuncAttributeMaxDynamicSharedMemorySize,
                         PROJ_SMEM);
    cudaFuncSetAttribute(attn_kernel, cudaFuncAttributeMaxDynamicSharedMemorySize,
                         SMEM_BYTES);

    dim3 gproj(NPOS / 128, 320 / 64, NB);   // (32, 5, 4) = 640
    proj_kernel<<<gproj, 256, PROJ_SMEM>>>(x, w1, w2, w3);

    dim3 gqk(NPOS / 128, NB);               // (32, 4)
    qkmax_kernel<<<gqk, 512>>>();

    dim3 gattn(NPOS / QM, NB);              // (32, 4)
    attn_kernel<<<gattn, THREADS, SMEM_BYTES>>>(x, out);
}